// round 14
// baseline (speedup 1.0000x reference)
#include <cuda_runtime.h>
#include <cuda_fp16.h>
#include <math.h>

// TropicalHashGrid: 16-level hash-grid encoding, N=2^21 points, F=2 feats/level.
// Levels 0-5 via dense cube tables (level 5 baked from its hash),
// levels 6-15 spatially hashed. fp16 tables (tcnn-style).
//
// R14 = R13 with the evict_last hint expressed via createpolicy +
// ld.global.nc.L2::cache_hint (sm_103a ptxas rejects the direct
// .L2::evict_last qualifier on non-256-bit loads). Changes vs R12 (463us):
//  - table gathers carry an L2 evict_last policy -> streaming output stops
//    evicting the 68MB table set (R12 moved ~290MB of table re-fetch)
//  - ONE fused prologue kernel; build_hash restructured to coalesced float4

#define L_LEVELS   16
#define HASHMAP_SZ (1u << 19)
#define HASH_MASK  (HASHMAP_SZ - 1u)
#define P_PER      (1 << 17)                // uint4 entries per level in M16
#define PRIME_Y    2654435761u
#define PRIME_Z    805459861u
#define NUM_DENSE  6                        // levels 0..5 via cube tables
#define NUM_HASH   (L_LEVELS - NUM_DENSE)   // 10
#define BLOCK_T    128

// Scratch (static __device__: allocation-free). Total ~68MB.
#define DENSE_TOTAL_MAX 871000
__device__ __align__(128) uint4 g_dcube[2 * DENSE_TOTAL_MAX];     // ~27.9MB
__device__ __align__(16) unsigned g_hash[NUM_HASH * HASHMAP_SZ];  // 20MB (A)
__device__ __align__(16) uint4    g_m16[NUM_HASH * P_PER];        // 20MB (M16)

struct LevelParams {
    float scale[L_LEVELS];
    int   res[L_LEVELS];
    int   doff[NUM_DENSE];
};

// ------------- bit-cast helpers -------------
__device__ __forceinline__ unsigned h2_to_u(__half2 h) {
    return *reinterpret_cast<unsigned*>(&h);
}
__device__ __forceinline__ float2 h2f(unsigned u) {
    return __half22float2(*reinterpret_cast<__half2*>(&u));
}
// Select component j (0..3) of a uint4.
__device__ __forceinline__ unsigned comp4(const uint4 q, unsigned j) {
    const unsigned lo = (j & 1u) ? q.y : q.x;
    const unsigned hi = (j & 1u) ? q.w : q.z;
    return (j & 2u) ? hi : lo;
}
// L2 evict_last table loads via createpolicy + cache_hint (sm_80+ form that
// sm_103a ptxas accepts). Keeps the 68MB table set resident while the 256MB
// output streams through with __stcs (evict-first).
__device__ __forceinline__ uint4 ldg_el4(const uint4* p) {
    uint4 q;
    asm("{\n\t"
        ".reg .b64 pol;\n\t"
        "createpolicy.fractional.L2::evict_last.b64 pol, 1.0;\n\t"
        "ld.global.nc.L2::cache_hint.v4.u32 {%0,%1,%2,%3}, [%4], pol;\n\t"
        "}"
        : "=r"(q.x), "=r"(q.y), "=r"(q.z), "=r"(q.w) : "l"(p));
    return q;
}
__device__ __forceinline__ unsigned ldg_el1(const unsigned* p) {
    unsigned q;
    asm("{\n\t"
        ".reg .b64 pol;\n\t"
        "createpolicy.fractional.L2::evict_last.b64 pol, 1.0;\n\t"
        "ld.global.nc.L2::cache_hint.u32 %0, [%1], pol;\n\t"
        "}"
        : "=r"(q) : "l"(p));
    return q;
}

// ------------- fused prologue: A + M16 + dense cubes 0-4 + cube 5 -----------
// Thread ranges: [0,hTotal): hash tables; [hTotal,+dTotal): dense 0-4;
// then d5Total for level 5.
__global__ void build_all_kernel(const float* __restrict__ table,
                                 LevelParams lp,
                                 int hTotal, int dTotal, int d5Total,
                                 int res5, int doff5)
{
    int i = blockIdx.x * blockDim.x + threadIdx.x;

    if (i < hTotal) {
        // One thread per 4-entry output group j of level lvl.
        const int lvl = i >> 17;
        const int j   = i & ((1 << 17) - 1);
        const float4* __restrict__ src4 =
            reinterpret_cast<const float4*>(table)
            + ((size_t)(lvl + NUM_DENSE) << 18);      // 2^18 float4 per level
        const float4 a = __ldg(src4 + 2 * j);
        const float4 b = __ldg(src4 + 2 * j + 1);
        uint4 A;
        A.x = h2_to_u(__floats2half2_rn(a.x, a.y));
        A.y = h2_to_u(__floats2half2_rn(a.z, a.w));
        A.z = h2_to_u(__floats2half2_rn(b.x, b.y));
        A.w = h2_to_u(__floats2half2_rn(b.z, b.w));
        reinterpret_cast<uint4*>(g_hash + (size_t)lvl * HASHMAP_SZ)[j] = A;

        // M16 group (G,q): entries {16G+q, 16G+7-q, 16G+8+q, 16G+15-q}.
        // Same 128B line the warp just fetched -> L1 hits.
        const int G = j >> 2, q = j & 3;
        const float2* __restrict__ src2 =
            reinterpret_cast<const float2*>(table)
            + ((size_t)(lvl + NUM_DENSE) << 19) + ((size_t)G << 4);
        const float2 e0 = __ldg(src2 + q);
        const float2 e1 = __ldg(src2 + (7 - q));
        const float2 e2 = __ldg(src2 + (8 + q));
        const float2 e3 = __ldg(src2 + (15 - q));
        uint4 M;
        M.x = h2_to_u(__floats2half2_rn(e0.x, e0.y));
        M.y = h2_to_u(__floats2half2_rn(e1.x, e1.y));
        M.z = h2_to_u(__floats2half2_rn(e2.x, e2.y));
        M.w = h2_to_u(__floats2half2_rn(e3.x, e3.y));
        g_m16[(size_t)lvl * P_PER + j] = M;
        return;
    }
    i -= hTotal;

    if (i < dTotal) {
        // Dense cube for clamped levels 0-4.
        int l = 0;
        #pragma unroll
        for (int k = 1; k < 5; ++k) if (i >= lp.doff[k]) l = k;
        const int flat = i - lp.doff[l];
        const int res  = lp.res[l];
        const int r2   = res * res;
        const int z    = flat / r2;
        const int rem  = flat - z * r2;
        const int y    = rem / res;
        const int x    = rem - y * res;
        const int x1   = min(x + 1, res - 1);
        const int y1   = min(y + 1, res - 1);
        const int z1   = min(z + 1, res - 1);
        const float2* __restrict__ tbl =
            reinterpret_cast<const float2*>(table) + (size_t)l * HASHMAP_SZ;
        #pragma unroll
        for (int h = 0; h < 2; ++h) {
            const int zz = (h ? z1 : z) * r2;
            const float2 c00 = tbl[x  + y  * res + zz];
            const float2 c10 = tbl[x1 + y  * res + zz];
            const float2 c01 = tbl[x  + y1 * res + zz];
            const float2 c11 = tbl[x1 + y1 * res + zz];
            uint4 qq;
            qq.x = h2_to_u(__floats2half2_rn(c00.x, c00.y));
            qq.y = h2_to_u(__floats2half2_rn(c10.x, c10.y));
            qq.z = h2_to_u(__floats2half2_rn(c01.x, c01.y));
            qq.w = h2_to_u(__floats2half2_rn(c11.x, c11.y));
            g_dcube[2 * i + h] = qq;
        }
        return;
    }
    i -= dTotal;

    if (i < d5Total) {
        // Level 5 cube: bake tbl[hash(corner)] per cell (no clamping).
        const int r2  = res5 * res5;
        const int z   = i / r2;
        const int rem = i - z * r2;
        const int y   = rem / res5;
        const int x   = rem - y * res5;
        const float2* __restrict__ tbl =
            reinterpret_cast<const float2*>(table) + (size_t)5 * HASHMAP_SZ;
        const unsigned hx0 = (unsigned)x,           hx1 = hx0 + 1u;
        const unsigned hy0 = (unsigned)y * PRIME_Y, hy1 = hy0 + PRIME_Y;
        #pragma unroll
        for (int h = 0; h < 2; ++h) {
            const unsigned hz = ((unsigned)z + (unsigned)h) * PRIME_Z;
            const float2 c00 = tbl[(hx0 ^ hy0 ^ hz) & HASH_MASK];
            const float2 c10 = tbl[(hx1 ^ hy0 ^ hz) & HASH_MASK];
            const float2 c01 = tbl[(hx0 ^ hy1 ^ hz) & HASH_MASK];
            const float2 c11 = tbl[(hx1 ^ hy1 ^ hz) & HASH_MASK];
            uint4 qq;
            qq.x = h2_to_u(__floats2half2_rn(c00.x, c00.y));
            qq.y = h2_to_u(__floats2half2_rn(c10.x, c10.y));
            qq.z = h2_to_u(__floats2half2_rn(c01.x, c01.y));
            qq.w = h2_to_u(__floats2half2_rn(c11.x, c11.y));
            g_dcube[2 * (doff5 + i) + h] = qq;
        }
    }
}

// ------------- main kernel -------------
__global__ void __launch_bounds__(BLOCK_T, 8)
hashgrid_kernel(const float* __restrict__ xs,
                float* __restrict__ out,
                int n, LevelParams lp)
{
    __shared__ float sbuf[BLOCK_T * 33];   // coords, then results (stride 33)

    const int tid  = threadIdx.x;
    const int lane = tid & 31;
    const int wrow = (tid >> 5) * 32;      // warp's first row within block
    const int p0   = blockIdx.x * BLOCK_T;
    const int pt   = p0 + tid;

    float px, py, pz;
    if (p0 + BLOCK_T <= n) {
        if (tid < 96) {
            const float4 v = __ldg(reinterpret_cast<const float4*>(
                                       xs + (size_t)p0 * 3) + tid);
            reinterpret_cast<float4*>(sbuf)[tid] = v;
        }
        __syncthreads();
        px = sbuf[tid * 3 + 0];
        py = sbuf[tid * 3 + 1];
        pz = sbuf[tid * 3 + 2];
        __syncthreads();
    } else {
        const int ptc = (pt < n) ? pt : (n - 1);
        px = xs[(size_t)ptc * 3 + 0];
        py = xs[(size_t)ptc * 3 + 1];
        pz = xs[(size_t)ptc * 3 + 2];
    }

    // ---- Dense-treated levels 0..5: 32B cube entry, lane-pair loads ----
    #pragma unroll 1
    for (int l = 0; l < NUM_DENSE; ++l) {
        const float scale = lp.scale[l];
        const int   res   = lp.res[l];

        // Unfused mul+add to match reference elementwise x*scale + 0.5.
        const float posx = __fadd_rn(__fmul_rn(px, scale), 0.5f);
        const float posy = __fadd_rn(__fmul_rn(py, scale), 0.5f);
        const float posz = __fadd_rn(__fmul_rn(pz, scale), 0.5f);
        const float pfx = floorf(posx), pfy = floorf(posy), pfz = floorf(posz);
        const float fx = posx - pfx, fy = posy - pfy, fz = posz - pfz;
        const int gx = (int)pfx, gy = (int)pfy, gz = (int)pfz;
        const int base = lp.doff[l] + gx + (gy + gz * res) * res;

        #pragma unroll
        for (int p = 0; p < 2; ++p) {
            const int   q   = 16 * p + (lane >> 1);
            const int   bq  = __shfl_sync(0xffffffffu, base, q);
            const float qfx = __shfl_sync(0xffffffffu, fx, q);
            const float qfy = __shfl_sync(0xffffffffu, fy, q);
            const float qfz = __shfl_sync(0xffffffffu, fz, q);

            const uint4 h = ldg_el4(g_dcube + 2 * bq + (lane & 1));

            const float wz  = (lane & 1) ? qfz : (1.0f - qfz);
            const float wx1 = qfx, wx0 = 1.0f - qfx;
            const float wy1 = qfy, wy0 = 1.0f - qfy;
            const float w00 = wx0 * wy0 * wz, w10 = wx1 * wy0 * wz;
            const float w01 = wx0 * wy1 * wz, w11 = wx1 * wy1 * wz;
            const float2 c00 = h2f(h.x), c10 = h2f(h.y);
            const float2 c01 = h2f(h.z), c11 = h2f(h.w);

            float rx = w00 * c00.x;
            float ry = w00 * c00.y;
            rx = fmaf(w10, c10.x, rx); ry = fmaf(w10, c10.y, ry);
            rx = fmaf(w01, c01.x, rx); ry = fmaf(w01, c01.y, ry);
            rx = fmaf(w11, c11.x, rx); ry = fmaf(w11, c11.y, ry);

            rx += __shfl_xor_sync(0xffffffffu, rx, 1);
            ry += __shfl_xor_sync(0xffffffffu, ry, 1);

            if ((lane & 1) == 0) {
                const int row = wrow + q;
                sbuf[row * 33 + 2 * l + 0] = rx;
                sbuf[row * 33 + 2 * l + 1] = ry;
            }
        }
    }

    // ---- Hash levels 6..15: idx = (x ^ y*P1 ^ z*P2) & mask ----
    // x-corner pair (a, a^m), m = hx^(hx+1) = 2^k-1:
    //   m<=3       -> aligned 4-group of A   (one LDG.128); partner slot s^m
    //   m==7,m==15 -> mirror group of M16    (one LDG.128); partner s^1 / s^3
    //   m>=31      -> two scalar loads (prob 1/16)
    #pragma unroll 1
    for (int l = NUM_DENSE; l < L_LEVELS; ++l) {
        const int hl = l - NUM_DENSE;
        const unsigned* __restrict__ tbl = g_hash + (size_t)hl * HASHMAP_SZ;
        const uint4* __restrict__ tA = reinterpret_cast<const uint4*>(tbl);
        const uint4* __restrict__ tM = g_m16 + (size_t)hl * P_PER;
        const float scale = lp.scale[l];

        const float posx = __fadd_rn(__fmul_rn(px, scale), 0.5f);
        const float posy = __fadd_rn(__fmul_rn(py, scale), 0.5f);
        const float posz = __fadd_rn(__fmul_rn(pz, scale), 0.5f);
        const float pfx = floorf(posx), pfy = floorf(posy), pfz = floorf(posz);
        const float fx = posx - pfx, fy = posy - pfy, fz = posz - pfz;

        const unsigned hx0 = (unsigned)(int)pfx;
        const unsigned hx1 = hx0 + 1u;
        const unsigned hy0 = (unsigned)(int)pfy * PRIME_Y;
        const unsigned hy1 = hy0 + PRIME_Y;
        const unsigned hz0 = (unsigned)(int)pfz * PRIME_Z;
        const unsigned hz1 = hz0 + PRIME_Z;

        const unsigned m  = hx0 ^ hx1;         // 1,3,7,15,31,...
        const bool mA  = (m <= 3u);
        const bool prd = (m <= 15u);           // paired via A or M16
        const unsigned sxor = mA ? m : ((m == 7u) ? 1u : 3u);

        unsigned av[4], s0[4];
        const uint4* gp[4];
        {
            const unsigned hyz[4] = { hy0 ^ hz0, hy0 ^ hz1,
                                      hy1 ^ hz0, hy1 ^ hz1 };
            #pragma unroll
            for (int c = 0; c < 4; ++c) {
                const unsigned a = (hx0 ^ hyz[c]) & HASH_MASK;
                av[c] = a;
                const unsigned j7 = a & 7u;
                const unsigned q  = min(j7, 7u - j7);
                const unsigned offA = a >> 2;
                const unsigned offM = ((a >> 4) << 2) | q;
                const unsigned sA = a & 3u;
                const unsigned sM = (((a >> 3) & 1u) << 1) | ((a >> 2) & 1u);
                gp[c] = mA ? (tA + offA) : (tM + offM);
                s0[c] = mA ? sA : sM;
            }
        }

        // Issue all loads back-to-back (predicated) to keep MLP high.
        uint4 qv[4];
        #pragma unroll
        for (int c = 0; c < 4; ++c) if (prd) qv[c] = ldg_el4(gp[c]);
        unsigned u0[4], u1[4];
        #pragma unroll
        for (int c = 0; c < 4; ++c) {
            if (!prd) {
                u0[c] = ldg_el1(tbl + av[c]);
                u1[c] = ldg_el1(tbl + ((av[c] ^ m) & HASH_MASK));
            }
        }

        float2 f[8];
        #pragma unroll
        for (int c = 0; c < 4; ++c) {
            if (prd) {
                f[c]     = h2f(comp4(qv[c], s0[c]));
                f[4 + c] = h2f(comp4(qv[c], s0[c] ^ sxor));
            } else {
                f[c]     = h2f(u0[c]);
                f[4 + c] = h2f(u1[c]);
            }
        }

        // Trilinear blend (z fastest among the 4 combos, x split at f[4..7]).
        const float wx1 = fx, wx0 = 1.0f - fx;
        const float wy1 = fy, wy0 = 1.0f - fy;
        const float wz1 = fz, wz0 = 1.0f - fz;
        const float wxy00 = wx0 * wy0, wxy01 = wx0 * wy1;
        const float wxy10 = wx1 * wy0, wxy11 = wx1 * wy1;
        float w[8];
        w[0] = wxy00 * wz0; w[1] = wxy00 * wz1;
        w[2] = wxy01 * wz0; w[3] = wxy01 * wz1;
        w[4] = wxy10 * wz0; w[5] = wxy10 * wz1;
        w[6] = wxy11 * wz0; w[7] = wxy11 * wz1;

        float r0 = w[0] * f[0].x;
        float r1 = w[0] * f[0].y;
        #pragma unroll
        for (int j = 1; j < 8; ++j) {
            r0 = fmaf(w[j], f[j].x, r0);
            r1 = fmaf(w[j], f[j].y, r1);
        }

        sbuf[tid * 33 + 2 * l + 0] = r0;
        sbuf[tid * 33 + 2 * l + 1] = r1;
    }

    __syncthreads();

    // Coalesced copy-out; streaming (evict-first) stores keep tables in L2.
    const int nvalid = min(BLOCK_T, n - p0);
    float* __restrict__ ob = out + (size_t)p0 * 32;
    const int total = nvalid * 32;
    #pragma unroll 4
    for (int k = tid; k < total; k += BLOCK_T) {
        __stcs(ob + k, sbuf[(k >> 5) * 33 + (k & 31)]);
    }
}

extern "C" void kernel_launch(void* const* d_in, const int* in_sizes, int n_in,
                              void* d_out, int out_size)
{
    const int n = out_size / (L_LEVELS * 2);   // out is [N, 32] float32

    const float* x   = (const float*)d_in[0];
    const float* tbl = (const float*)d_in[1];
    if (n_in >= 2 && in_sizes[0] != n * 3) {
        x   = (const float*)d_in[1];
        tbl = (const float*)d_in[0];
    }

    LevelParams lp;
    const double B = pow(2.0, 7.0 / 15.0);     // log2(2048/16)/15
    int off = 0;
    for (int l = 0; l < L_LEVELS; ++l) {
        const double s = 16.0 * pow(B, (double)l) - 1.0;
        lp.scale[l] = (float)s;
        lp.res[l]   = (int)ceil(s) + 1;
        if (l < NUM_DENSE) {
            lp.doff[l] = off;
            off += lp.res[l] * lp.res[l] * lp.res[l];
        }
    }
    const int dTotal  = lp.doff[5];            // 330,940 (levels 0-4)
    const int d5Total = off - lp.doff[5];      // 531,441 (level 5, res=81)
    const int hTotal  = NUM_HASH * (1 << 17);  // 1,310,720

    // Fused prologue (one launch; deterministic function of inputs).
    const int ptotal = hTotal + dTotal + d5Total;
    build_all_kernel<<<(ptotal + 255) / 256, 256>>>(
        tbl, lp, hTotal, dTotal, d5Total, lp.res[5], lp.doff[5]);

    const int grid = (n + BLOCK_T - 1) / BLOCK_T;
    hashgrid_kernel<<<grid, BLOCK_T>>>(x, (float*)d_out, n, lp);
}

// round 15
// speedup vs baseline: 1.0574x; 1.0574x over previous
#include <cuda_runtime.h>
#include <cuda_fp16.h>
#include <math.h>

// TropicalHashGrid: 16-level hash-grid encoding, N=2^21 points, F=2 feats/level.
// Levels 0-5 via dense cube tables (level 5 baked from its hash),
// levels 6-15 spatially hashed. fp16 tables (tcnn-style).
//
// R15 = recombination of measured winners:
//  - main kernel: R12 exactly (426.5us, __ldg loads — R14 showed the
//    createpolicy/cache_hint asm cost +27us for no traffic benefit)
//  - prologue: R14's fused single launch (~15us vs R12's 36.5us)

#define L_LEVELS   16
#define HASHMAP_SZ (1u << 19)
#define HASH_MASK  (HASHMAP_SZ - 1u)
#define P_PER      (1 << 17)                // uint4 entries per level in M16
#define PRIME_Y    2654435761u
#define PRIME_Z    805459861u
#define NUM_DENSE  6                        // levels 0..5 via cube tables
#define NUM_HASH   (L_LEVELS - NUM_DENSE)   // 10
#define BLOCK_T    128

// Scratch (static __device__: allocation-free). Total ~68MB.
#define DENSE_TOTAL_MAX 871000
__device__ __align__(128) uint4 g_dcube[2 * DENSE_TOTAL_MAX];     // ~27.9MB
__device__ __align__(16) unsigned g_hash[NUM_HASH * HASHMAP_SZ];  // 20MB (A)
__device__ __align__(16) uint4    g_m16[NUM_HASH * P_PER];        // 20MB (M16)

struct LevelParams {
    float scale[L_LEVELS];
    int   res[L_LEVELS];
    int   doff[NUM_DENSE];
};

// ------------- bit-cast helpers -------------
__device__ __forceinline__ unsigned h2_to_u(__half2 h) {
    return *reinterpret_cast<unsigned*>(&h);
}
__device__ __forceinline__ float2 h2f(unsigned u) {
    return __half22float2(*reinterpret_cast<__half2*>(&u));
}
// Select component j (0..3) of a uint4.
__device__ __forceinline__ unsigned comp4(const uint4 q, unsigned j) {
    const unsigned lo = (j & 1u) ? q.y : q.x;
    const unsigned hi = (j & 1u) ? q.w : q.z;
    return (j & 2u) ? hi : lo;
}

// ------------- fused prologue: A + M16 + dense cubes 0-4 + cube 5 -----------
// Thread ranges: [0,hTotal): hash tables; [hTotal,+dTotal): dense 0-4;
// then d5Total for level 5.
__global__ void build_all_kernel(const float* __restrict__ table,
                                 LevelParams lp,
                                 int hTotal, int dTotal, int d5Total,
                                 int res5, int doff5)
{
    int i = blockIdx.x * blockDim.x + threadIdx.x;

    if (i < hTotal) {
        // One thread per 4-entry output group j of level lvl.
        const int lvl = i >> 17;
        const int j   = i & ((1 << 17) - 1);
        const float4* __restrict__ src4 =
            reinterpret_cast<const float4*>(table)
            + ((size_t)(lvl + NUM_DENSE) << 18);      // 2^18 float4 per level
        const float4 a = __ldg(src4 + 2 * j);
        const float4 b = __ldg(src4 + 2 * j + 1);
        uint4 A;
        A.x = h2_to_u(__floats2half2_rn(a.x, a.y));
        A.y = h2_to_u(__floats2half2_rn(a.z, a.w));
        A.z = h2_to_u(__floats2half2_rn(b.x, b.y));
        A.w = h2_to_u(__floats2half2_rn(b.z, b.w));
        reinterpret_cast<uint4*>(g_hash + (size_t)lvl * HASHMAP_SZ)[j] = A;

        // M16 group (G,q): entries {16G+q, 16G+7-q, 16G+8+q, 16G+15-q}.
        // Same 128B line the warp just fetched -> L1 hits.
        const int G = j >> 2, q = j & 3;
        const float2* __restrict__ src2 =
            reinterpret_cast<const float2*>(table)
            + ((size_t)(lvl + NUM_DENSE) << 19) + ((size_t)G << 4);
        const float2 e0 = __ldg(src2 + q);
        const float2 e1 = __ldg(src2 + (7 - q));
        const float2 e2 = __ldg(src2 + (8 + q));
        const float2 e3 = __ldg(src2 + (15 - q));
        uint4 M;
        M.x = h2_to_u(__floats2half2_rn(e0.x, e0.y));
        M.y = h2_to_u(__floats2half2_rn(e1.x, e1.y));
        M.z = h2_to_u(__floats2half2_rn(e2.x, e2.y));
        M.w = h2_to_u(__floats2half2_rn(e3.x, e3.y));
        g_m16[(size_t)lvl * P_PER + j] = M;
        return;
    }
    i -= hTotal;

    if (i < dTotal) {
        // Dense cube for clamped levels 0-4.
        int l = 0;
        #pragma unroll
        for (int k = 1; k < 5; ++k) if (i >= lp.doff[k]) l = k;
        const int flat = i - lp.doff[l];
        const int res  = lp.res[l];
        const int r2   = res * res;
        const int z    = flat / r2;
        const int rem  = flat - z * r2;
        const int y    = rem / res;
        const int x    = rem - y * res;
        const int x1   = min(x + 1, res - 1);
        const int y1   = min(y + 1, res - 1);
        const int z1   = min(z + 1, res - 1);
        const float2* __restrict__ tbl =
            reinterpret_cast<const float2*>(table) + (size_t)l * HASHMAP_SZ;
        #pragma unroll
        for (int h = 0; h < 2; ++h) {
            const int zz = (h ? z1 : z) * r2;
            const float2 c00 = tbl[x  + y  * res + zz];
            const float2 c10 = tbl[x1 + y  * res + zz];
            const float2 c01 = tbl[x  + y1 * res + zz];
            const float2 c11 = tbl[x1 + y1 * res + zz];
            uint4 qq;
            qq.x = h2_to_u(__floats2half2_rn(c00.x, c00.y));
            qq.y = h2_to_u(__floats2half2_rn(c10.x, c10.y));
            qq.z = h2_to_u(__floats2half2_rn(c01.x, c01.y));
            qq.w = h2_to_u(__floats2half2_rn(c11.x, c11.y));
            g_dcube[2 * i + h] = qq;
        }
        return;
    }
    i -= dTotal;

    if (i < d5Total) {
        // Level 5 cube: bake tbl[hash(corner)] per cell (no clamping).
        const int r2  = res5 * res5;
        const int z   = i / r2;
        const int rem = i - z * r2;
        const int y   = rem / res5;
        const int x   = rem - y * res5;
        const float2* __restrict__ tbl =
            reinterpret_cast<const float2*>(table) + (size_t)5 * HASHMAP_SZ;
        const unsigned hx0 = (unsigned)x,           hx1 = hx0 + 1u;
        const unsigned hy0 = (unsigned)y * PRIME_Y, hy1 = hy0 + PRIME_Y;
        #pragma unroll
        for (int h = 0; h < 2; ++h) {
            const unsigned hz = ((unsigned)z + (unsigned)h) * PRIME_Z;
            const float2 c00 = tbl[(hx0 ^ hy0 ^ hz) & HASH_MASK];
            const float2 c10 = tbl[(hx1 ^ hy0 ^ hz) & HASH_MASK];
            const float2 c01 = tbl[(hx0 ^ hy1 ^ hz) & HASH_MASK];
            const float2 c11 = tbl[(hx1 ^ hy1 ^ hz) & HASH_MASK];
            uint4 qq;
            qq.x = h2_to_u(__floats2half2_rn(c00.x, c00.y));
            qq.y = h2_to_u(__floats2half2_rn(c10.x, c10.y));
            qq.z = h2_to_u(__floats2half2_rn(c01.x, c01.y));
            qq.w = h2_to_u(__floats2half2_rn(c11.x, c11.y));
            g_dcube[2 * (doff5 + i) + h] = qq;
        }
    }
}

// ------------- main kernel (R12 exactly) -------------
__global__ void __launch_bounds__(BLOCK_T, 8)
hashgrid_kernel(const float* __restrict__ xs,
                float* __restrict__ out,
                int n, LevelParams lp)
{
    __shared__ float sbuf[BLOCK_T * 33];   // coords, then results (stride 33)

    const int tid  = threadIdx.x;
    const int lane = tid & 31;
    const int wrow = (tid >> 5) * 32;      // warp's first row within block
    const int p0   = blockIdx.x * BLOCK_T;
    const int pt   = p0 + tid;

    float px, py, pz;
    if (p0 + BLOCK_T <= n) {
        if (tid < 96) {
            const float4 v = __ldg(reinterpret_cast<const float4*>(
                                       xs + (size_t)p0 * 3) + tid);
            reinterpret_cast<float4*>(sbuf)[tid] = v;
        }
        __syncthreads();
        px = sbuf[tid * 3 + 0];
        py = sbuf[tid * 3 + 1];
        pz = sbuf[tid * 3 + 2];
        __syncthreads();
    } else {
        const int ptc = (pt < n) ? pt : (n - 1);
        px = xs[(size_t)ptc * 3 + 0];
        py = xs[(size_t)ptc * 3 + 1];
        pz = xs[(size_t)ptc * 3 + 2];
    }

    // ---- Dense-treated levels 0..5: 32B cube entry, lane-pair loads ----
    #pragma unroll 1
    for (int l = 0; l < NUM_DENSE; ++l) {
        const float scale = lp.scale[l];
        const int   res   = lp.res[l];

        // Unfused mul+add to match reference elementwise x*scale + 0.5.
        const float posx = __fadd_rn(__fmul_rn(px, scale), 0.5f);
        const float posy = __fadd_rn(__fmul_rn(py, scale), 0.5f);
        const float posz = __fadd_rn(__fmul_rn(pz, scale), 0.5f);
        const float pfx = floorf(posx), pfy = floorf(posy), pfz = floorf(posz);
        const float fx = posx - pfx, fy = posy - pfy, fz = posz - pfz;
        const int gx = (int)pfx, gy = (int)pfy, gz = (int)pfz;
        const int base = lp.doff[l] + gx + (gy + gz * res) * res;

        #pragma unroll
        for (int p = 0; p < 2; ++p) {
            const int   q   = 16 * p + (lane >> 1);
            const int   bq  = __shfl_sync(0xffffffffu, base, q);
            const float qfx = __shfl_sync(0xffffffffu, fx, q);
            const float qfy = __shfl_sync(0xffffffffu, fy, q);
            const float qfz = __shfl_sync(0xffffffffu, fz, q);

            const uint4 h = __ldg(g_dcube + 2 * bq + (lane & 1));

            const float wz  = (lane & 1) ? qfz : (1.0f - qfz);
            const float wx1 = qfx, wx0 = 1.0f - qfx;
            const float wy1 = qfy, wy0 = 1.0f - qfy;
            const float w00 = wx0 * wy0 * wz, w10 = wx1 * wy0 * wz;
            const float w01 = wx0 * wy1 * wz, w11 = wx1 * wy1 * wz;
            const float2 c00 = h2f(h.x), c10 = h2f(h.y);
            const float2 c01 = h2f(h.z), c11 = h2f(h.w);

            float rx = w00 * c00.x;
            float ry = w00 * c00.y;
            rx = fmaf(w10, c10.x, rx); ry = fmaf(w10, c10.y, ry);
            rx = fmaf(w01, c01.x, rx); ry = fmaf(w01, c01.y, ry);
            rx = fmaf(w11, c11.x, rx); ry = fmaf(w11, c11.y, ry);

            rx += __shfl_xor_sync(0xffffffffu, rx, 1);
            ry += __shfl_xor_sync(0xffffffffu, ry, 1);

            if ((lane & 1) == 0) {
                const int row = wrow + q;
                sbuf[row * 33 + 2 * l + 0] = rx;
                sbuf[row * 33 + 2 * l + 1] = ry;
            }
        }
    }

    // ---- Hash levels 6..15: idx = (x ^ y*P1 ^ z*P2) & mask ----
    // x-corner pair (a, a^m), m = hx^(hx+1) = 2^k-1:
    //   m<=3       -> aligned 4-group of A   (one LDG.128); partner slot s^m
    //   m==7,m==15 -> mirror group of M16    (one LDG.128); partner s^1 / s^3
    //   m>=31      -> two scalar loads (prob 1/16)
    #pragma unroll 1
    for (int l = NUM_DENSE; l < L_LEVELS; ++l) {
        const int hl = l - NUM_DENSE;
        const unsigned* __restrict__ tbl = g_hash + (size_t)hl * HASHMAP_SZ;
        const uint4* __restrict__ tA = reinterpret_cast<const uint4*>(tbl);
        const uint4* __restrict__ tM = g_m16 + (size_t)hl * P_PER;
        const float scale = lp.scale[l];

        const float posx = __fadd_rn(__fmul_rn(px, scale), 0.5f);
        const float posy = __fadd_rn(__fmul_rn(py, scale), 0.5f);
        const float posz = __fadd_rn(__fmul_rn(pz, scale), 0.5f);
        const float pfx = floorf(posx), pfy = floorf(posy), pfz = floorf(posz);
        const float fx = posx - pfx, fy = posy - pfy, fz = posz - pfz;

        const unsigned hx0 = (unsigned)(int)pfx;
        const unsigned hx1 = hx0 + 1u;
        const unsigned hy0 = (unsigned)(int)pfy * PRIME_Y;
        const unsigned hy1 = hy0 + PRIME_Y;
        const unsigned hz0 = (unsigned)(int)pfz * PRIME_Z;
        const unsigned hz1 = hz0 + PRIME_Z;

        const unsigned m  = hx0 ^ hx1;         // 1,3,7,15,31,...
        const bool mA  = (m <= 3u);
        const bool prd = (m <= 15u);           // paired via A or M16
        const unsigned sxor = mA ? m : ((m == 7u) ? 1u : 3u);

        unsigned av[4], s0[4];
        const uint4* gp[4];
        {
            const unsigned hyz[4] = { hy0 ^ hz0, hy0 ^ hz1,
                                      hy1 ^ hz0, hy1 ^ hz1 };
            #pragma unroll
            for (int c = 0; c < 4; ++c) {
                const unsigned a = (hx0 ^ hyz[c]) & HASH_MASK;
                av[c] = a;
                const unsigned j7 = a & 7u;
                const unsigned q  = min(j7, 7u - j7);
                const unsigned offA = a >> 2;
                const unsigned offM = ((a >> 4) << 2) | q;
                const unsigned sA = a & 3u;
                const unsigned sM = (((a >> 3) & 1u) << 1) | ((a >> 2) & 1u);
                gp[c] = mA ? (tA + offA) : (tM + offM);
                s0[c] = mA ? sA : sM;
            }
        }

        // Issue all loads back-to-back (predicated) to keep MLP high.
        uint4 qv[4];
        #pragma unroll
        for (int c = 0; c < 4; ++c) if (prd) qv[c] = __ldg(gp[c]);
        unsigned u0[4], u1[4];
        #pragma unroll
        for (int c = 0; c < 4; ++c) {
            if (!prd) {
                u0[c] = __ldg(tbl + av[c]);
                u1[c] = __ldg(tbl + ((av[c] ^ m) & HASH_MASK));
            }
        }

        float2 f[8];
        #pragma unroll
        for (int c = 0; c < 4; ++c) {
            if (prd) {
                f[c]     = h2f(comp4(qv[c], s0[c]));
                f[4 + c] = h2f(comp4(qv[c], s0[c] ^ sxor));
            } else {
                f[c]     = h2f(u0[c]);
                f[4 + c] = h2f(u1[c]);
            }
        }

        // Trilinear blend (z fastest among the 4 combos, x split at f[4..7]).
        const float wx1 = fx, wx0 = 1.0f - fx;
        const float wy1 = fy, wy0 = 1.0f - fy;
        const float wz1 = fz, wz0 = 1.0f - fz;
        const float wxy00 = wx0 * wy0, wxy01 = wx0 * wy1;
        const float wxy10 = wx1 * wy0, wxy11 = wx1 * wy1;
        float w[8];
        w[0] = wxy00 * wz0; w[1] = wxy00 * wz1;
        w[2] = wxy01 * wz0; w[3] = wxy01 * wz1;
        w[4] = wxy10 * wz0; w[5] = wxy10 * wz1;
        w[6] = wxy11 * wz0; w[7] = wxy11 * wz1;

        float r0 = w[0] * f[0].x;
        float r1 = w[0] * f[0].y;
        #pragma unroll
        for (int j = 1; j < 8; ++j) {
            r0 = fmaf(w[j], f[j].x, r0);
            r1 = fmaf(w[j], f[j].y, r1);
        }

        sbuf[tid * 33 + 2 * l + 0] = r0;
        sbuf[tid * 33 + 2 * l + 1] = r1;
    }

    __syncthreads();

    // Coalesced copy-out; streaming stores keep tables resident in L2.
    const int nvalid = min(BLOCK_T, n - p0);
    float* __restrict__ ob = out + (size_t)p0 * 32;
    const int total = nvalid * 32;
    #pragma unroll 4
    for (int k = tid; k < total; k += BLOCK_T) {
        __stcs(ob + k, sbuf[(k >> 5) * 33 + (k & 31)]);
    }
}

extern "C" void kernel_launch(void* const* d_in, const int* in_sizes, int n_in,
                              void* d_out, int out_size)
{
    const int n = out_size / (L_LEVELS * 2);   // out is [N, 32] float32

    const float* x   = (const float*)d_in[0];
    const float* tbl = (const float*)d_in[1];
    if (n_in >= 2 && in_sizes[0] != n * 3) {
        x   = (const float*)d_in[1];
        tbl = (const float*)d_in[0];
    }

    LevelParams lp;
    const double B = pow(2.0, 7.0 / 15.0);     // log2(2048/16)/15
    int off = 0;
    for (int l = 0; l < L_LEVELS; ++l) {
        const double s = 16.0 * pow(B, (double)l) - 1.0;
        lp.scale[l] = (float)s;
        lp.res[l]   = (int)ceil(s) + 1;
        if (l < NUM_DENSE) {
            lp.doff[l] = off;
            off += lp.res[l] * lp.res[l] * lp.res[l];
        }
    }
    const int dTotal  = lp.doff[5];            // 330,940 (levels 0-4)
    const int d5Total = off - lp.doff[5];      // 531,441 (level 5, res=81)
    const int hTotal  = NUM_HASH * (1 << 17);  // 1,310,720

    // Fused prologue (one launch; deterministic function of inputs).
    const int ptotal = hTotal + dTotal + d5Total;
    build_all_kernel<<<(ptotal + 255) / 256, 256>>>(
        tbl, lp, hTotal, dTotal, d5Total, lp.res[5], lp.doff[5]);

    const int grid = (n + BLOCK_T - 1) / BLOCK_T;
    hashgrid_kernel<<<grid, BLOCK_T>>>(x, (float*)d_out, n, lp);
}